// round 13
// baseline (speedup 1.0000x reference)
#include <cuda_runtime.h>
#include <cstdint>

#define BB 128
#define TT 64
#define WW 200
#define EE 128
#define NN 128
#define PADROW 132   // row stride in floats
#define THREADS 1024

typedef unsigned long long u64;

// ---- f32x2 packed helpers ----
__device__ __forceinline__ u64 pk2(float lo, float hi) {
    u64 r; asm("mov.b64 %0,{%1,%2};" : "=l"(r) : "f"(lo), "f"(hi)); return r;
}
__device__ __forceinline__ u64 add2(u64 a, u64 b) {
    u64 r; asm("add.rn.f32x2 %0,%1,%2;" : "=l"(r) : "l"(a), "l"(b)); return r;
}
__device__ __forceinline__ u64 fma2(u64 a, u64 b, u64 c) {
    u64 r; asm("fma.rn.f32x2 %0,%1,%2,%3;" : "=l"(r) : "l"(a), "l"(b), "l"(c)); return r;
}
__device__ __forceinline__ void unpk2(u64 p, float& lo, float& hi) {
    asm("mov.b64 {%0,%1},%2;" : "=f"(lo), "=f"(hi) : "l"(p));
}
union F4U { float4 v; u64 p[2]; float f[4]; };

#define ABS2 0x7FFFFFFF7FFFFFFFULL

// ---- device scratch ----
__device__ float g_hpS[BB * TT * NN];   // hp[b,t,n] * |hw[n]|
__device__ float g_u[NN];               // u[e] = sum_n hw[n] * Wq[n,e]
__device__ float g_att[BB * TT * WW];   // exp'd attention [b][t][w]

// =====================================================================
// Kernel A: hpS precompute (+ u vector from block 0)
// =====================================================================
#define SMEM_A_BYTES ((128 * PADROW + 64 * 128) * 4)

__global__ __launch_bounds__(256) void prep_kernel(
    const float* __restrict__ tvecs, const float* __restrict__ W_w,
    const float* __restrict__ h_w, const int* __restrict__ titems)
{
    extern __shared__ float sm[];
    float* sWp = sm;                 // [128][PADROW]
    float* sq  = sm + 128 * PADROW;  // [64][128]
    const int b = blockIdx.x, tid = threadIdx.x;

    for (int idx = tid; idx < 128 * 32; idx += 256) {
        int row = idx >> 5, c = idx & 31;
        float4 v = *reinterpret_cast<const float4*>(W_w + row * 256 + c * 4);
        float a = fabsf(h_w[row]);
        v.x *= a; v.y *= a; v.z *= a; v.w *= a;
        *reinterpret_cast<float4*>(sWp + row * PADROW + c * 4) = v;
    }
    for (int idx = tid; idx < 64 * 32; idx += 256) {
        int t = idx >> 5, c = idx & 31;
        int it = titems[b * TT + t];
        float4 v = *reinterpret_cast<const float4*>(tvecs + (size_t)it * EE + c * 4);
        *reinterpret_cast<float4*>(sq + t * 128 + c * 4) = v;
    }
    __syncthreads();

    for (int idx = tid; idx < TT * NN; idx += 256) {
        int n = idx & 127, t = idx >> 7;
        const F4U* qr = reinterpret_cast<const F4U*>(sq + t * 128);
        const F4U* wr = reinterpret_cast<const F4U*>(sWp + n * PADROW);
        u64 acc = 0;
        #pragma unroll
        for (int c = 0; c < 32; c++) {
            F4U q = qr[c], w = wr[c];
            acc = fma2(q.p[0], w.p[0], acc);
            acc = fma2(q.p[1], w.p[1], acc);
        }
        float lo, hi; unpk2(acc, lo, hi);
        g_hpS[(b * TT + t) * NN + n] = lo + hi;
    }

    if (b == 0) {
        for (int e = tid; e < EE; e += 256) {
            float acc = 0.f;
            #pragma unroll 8
            for (int n = 0; n < NN; n++)
                acc = fmaf(h_w[n], W_w[n * 256 + 128 + e], acc);
            g_u[e] = acc;
        }
    }
}

// =====================================================================
// Kernel B: per-batch attention. One CTA per b, 1024 threads.
// =====================================================================
#define OFF_SK 0                       // k       [200][132]
#define OFF_HQ (WW * PADROW)           // hqS     [200][132]; sev[w][68] in 4b
#define OFF_UN (2 * WW * PADROW)       // scratch: Wq tile [16][132] / sHp [16][132]
#define OFF_SU (OFF_UN + 3264)         // u       [128]
#define OFF_BQ (OFF_SU + 128)          // 0.5*Bq  [200] (+8 pad)
#define OFF_WB (OFF_BQ + 208)          // Wb*|hw| [128]
#define OFF_MK (OFF_WB + 128)          // mask flags (1B per w; 56 floats)
#define OFF_MS (OFF_MK + 56)           // misc [8]: [0]=norm
#define OFF_SUMS (OFF_MS + 8)          // per-t exp sums [64]
#define SMEM_B_FLOATS (OFF_SUMS + 64)
#define SMEM_B_BYTES (SMEM_B_FLOATS * 4)
#define SEVST 68                       // sev row stride (floats)

__global__ __launch_bounds__(THREADS, 1) void main_kernel(
    const float* __restrict__ cvecs, const float* __restrict__ W_w,
    const float* __restrict__ W_b,   const float* __restrict__ h_w,
    const int* __restrict__ citems,  const uint32_t* __restrict__ mask,
    float* __restrict__ out)
{
    extern __shared__ float sm[];
    float* sk    = sm + OFF_SK;
    float* shq   = sm + OFF_HQ;   // hq in phases 3-4a; sev in 4b
    float* sWq   = sm + OFF_UN;   // Wq tile in 3; sHp in 4a
    float* su    = sm + OFF_SU;
    float* sBq   = sm + OFF_BQ;
    float* swb   = sm + OFF_WB;
    unsigned char* smask = reinterpret_cast<unsigned char*>(sm + OFF_MK);
    float* smisc = sm + OFF_MS;
    float* ssum  = sm + OFF_SUMS;

    const int b = blockIdx.x, tid = threadIdx.x;
    const int warp = tid >> 5, lane = tid & 31;

    // ---- phase 1: loads ----
    if (tid < WW) smask[tid] = (mask[b * WW + tid] != 0u) ? 1 : 0;
    if (tid >= 256 && tid < 256 + 128) {
        int n = tid - 256;
        swb[n] = W_b[n] * fabsf(h_w[n]);
    }
    if (tid >= 384 && tid < 384 + 32) {
        int c = tid - 384;
        reinterpret_cast<float4*>(su)[c] = reinterpret_cast<const float4*>(g_u)[c];
    }
    for (int r = warp; r < WW; r += 32) {
        int idx = citems[b * WW + r];
        float4 v = reinterpret_cast<const float4*>(cvecs + (size_t)idx * EE)[lane];
        reinterpret_cast<float4*>(sk + r * PADROW)[lane] = v;
    }
    __syncthreads();

    // ---- phase 2: 0.5*Bq[w] = 0.5*k[w]·u ; mask count -> norm ----
    if (tid < WW) {
        const F4U* kr = reinterpret_cast<const F4U*>(sk + tid * PADROW);
        const F4U* ur = reinterpret_cast<const F4U*>(su);
        u64 acc = 0;
        #pragma unroll
        for (int c = 0; c < 32; c++) {
            F4U k = kr[c], u = ur[c];
            acc = fma2(k.p[0], u.p[0], acc);
            acc = fma2(k.p[1], u.p[1], acc);
        }
        float lo, hi; unpk2(acc, lo, hi);
        sBq[tid] = 0.5f * (lo + hi);
    }
    if (warp == 16) {
        int s = 0;
        #pragma unroll
        for (int c = 0; c < 7; c++) {
            int w = lane + 32 * c;
            if (w < WW) s += (int)smask[w];
        }
        #pragma unroll
        for (int o = 16; o; o >>= 1) s += __shfl_xor_sync(0xffffffffu, s, o);
        if (lane == 0) smisc[0] = sqrtf(1000.0f - (float)s);
    }

    // ---- phase 3: hqS = (k·Wq + Wb)*|hw|, 8 n-tiles of 16, 2w x 2n blocking ----
    for (int tile = 0; tile < 8; tile++) {
        __syncthreads();
        if (tid < 512) {
            int row = tid >> 5, c = tid & 31;  // 16 rows x 32 float4-chunks
            int n = tile * 16 + row;
            float4 v = *reinterpret_cast<const float4*>(W_w + n * 256 + 128 + c * 4);
            float a = fabsf(h_w[n]);
            v.x *= a; v.y *= a; v.z *= a; v.w *= a;
            *reinterpret_cast<float4*>(sWq + row * PADROW + c * 4) = v;
        }
        __syncthreads();
        if (tid < 800) {
            int wp = tid >> 3, nq = tid & 7;   // w in {wp, wp+100}, n-local in {nq, nq+8}
            const F4U* kA = reinterpret_cast<const F4U*>(sk + wp * PADROW);
            const F4U* kB = reinterpret_cast<const F4U*>(sk + (wp + 100) * PADROW);
            const F4U* wA = reinterpret_cast<const F4U*>(sWq + nq * PADROW);
            const F4U* wB = reinterpret_cast<const F4U*>(sWq + (nq + 8) * PADROW);
            u64 aA0 = 0, aA1 = 0, aB0 = 0, aB1 = 0;
            #pragma unroll
            for (int c = 0; c < 32; c++) {
                F4U ka = kA[c], kb = kB[c], xa = wA[c], xb = wB[c];
                aA0 = fma2(ka.p[0], xa.p[0], aA0); aA0 = fma2(ka.p[1], xa.p[1], aA0);
                aA1 = fma2(ka.p[0], xb.p[0], aA1); aA1 = fma2(ka.p[1], xb.p[1], aA1);
                aB0 = fma2(kb.p[0], xa.p[0], aB0); aB0 = fma2(kb.p[1], xa.p[1], aB0);
                aB1 = fma2(kb.p[0], xb.p[0], aB1); aB1 = fma2(kb.p[1], xb.p[1], aB1);
            }
            float lo, hi;
            int n0 = tile * 16 + nq, n1 = n0 + 8;
            unpk2(aA0, lo, hi); shq[wp * PADROW + n0]         = lo + hi + swb[n0];
            unpk2(aA1, lo, hi); shq[wp * PADROW + n1]         = lo + hi + swb[n1];
            unpk2(aB0, lo, hi); shq[(wp + 100) * PADROW + n0] = lo + hi + swb[n0];
            unpk2(aB1, lo, hi); shq[(wp + 100) * PADROW + n1] = lo + hi + swb[n1];
        }
    }

    // ---- phase 4a: ev = exp(logit); flat (q, t-pair) tasks, dual accumulators ----
    const int j = lane & 7, g = lane >> 3;
    u64 sgn2[8];
    #pragma unroll
    for (int c = 0; c < 4; c++) {
        F4U h; h.v = reinterpret_cast<const float4*>(h_w)[j + 8 * c];
        sgn2[2 * c]     = pk2(h.f[0] >= 0.f ? 0.5f : -0.5f, h.f[1] >= 0.f ? 0.5f : -0.5f);
        sgn2[2 * c + 1] = pk2(h.f[2] >= 0.f ? 0.5f : -0.5f, h.f[3] >= 0.f ? 0.5f : -0.5f);
    }
    float* gatt = g_att + (size_t)b * TT * WW;
    const float* hpbase = g_hpS + (size_t)b * TT * NN;
    float* sHp = sWq;   // [16][PADROW]

    for (int qtr = 0; qtr < 4; qtr++) {
        __syncthreads();   // sHp/sWq free
        if (warp < 16) {
            float4 v = reinterpret_cast<const float4*>(hpbase + (qtr * 16 + warp) * NN)[lane];
            reinterpret_cast<float4*>(sHp + warp * PADROW)[lane] = v;
        }
        __syncthreads();

        // 400 tasks = 50 q x 8 t-pairs over 32 warps (max 13 vs avg 12.5)
        #pragma unroll 1
        for (int task = warp; task < 400; task += 32) {
            int q = task % 50;
            int tp = task / 50;            // t-pair 0..7
            const int w = 4 * q + g;
            u64 hq2[8];
            {
                const float4* hr = reinterpret_cast<const float4*>(shq + w * PADROW);
                #pragma unroll
                for (int c = 0; c < 4; c++) {
                    F4U x; x.v = hr[j + 8 * c];
                    hq2[2 * c] = x.p[0]; hq2[2 * c + 1] = x.p[1];
                }
            }
            const float bq = sBq[w];
            const int msk = smask[w];

            #pragma unroll
            for (int tt = 0; tt < 2; tt++) {
                int t2 = tp * 2 + tt;
                const float4* hpr = reinterpret_cast<const float4*>(sHp + t2 * PADROW);
                u64 acc0 = 0, acc1 = 0;
                #pragma unroll
                for (int c = 0; c < 4; c++) {
                    F4U x; x.v = hpr[j + 8 * c];
                    u64 v0 = add2(x.p[0], hq2[2 * c]) & ABS2;
                    u64 v1 = add2(x.p[1], hq2[2 * c + 1]) & ABS2;
                    acc0 = fma2(v0, sgn2[2 * c], acc0);
                    acc1 = fma2(v1, sgn2[2 * c + 1], acc1);
                }
                u64 a = add2(acc0, acc1);
                float lo, hi; unpk2(a, lo, hi);
                float s = lo + hi;
                s += __shfl_down_sync(0xffffffffu, s, 4, 8);
                s += __shfl_down_sync(0xffffffffu, s, 2, 8);
                s += __shfl_down_sync(0xffffffffu, s, 1, 8);
                if (j == 0) {
                    float ev = msk ? 0.f : __expf(s + bq);
                    gatt[(qtr * 16 + t2) * WW + w] = ev;
                }
            }
        }
    }
    __syncthreads();   // g_att complete; shq (hq) now dead

    // ---- phase 4b: stage ev -> sev[w][68] via coalesced LDG + STS.128 ----
    float* sev = shq;
    for (int idx = tid; idx < WW * 16; idx += THREADS) {   // (w, t-quad) pairs
        int tq = idx / WW, w = idx - tq * WW;
        float4 v;
        v.x = gatt[(4 * tq + 0) * WW + w];
        v.y = gatt[(4 * tq + 1) * WW + w];
        v.z = gatt[(4 * tq + 2) * WW + w];
        v.w = gatt[(4 * tq + 3) * WW + w];
        *reinterpret_cast<float4*>(sev + w * SEVST + 4 * tq) = v;
    }
    __syncthreads();

    // ---- sums: warp owns t = 2*warp, 2*warp+1 ----
    #pragma unroll
    for (int tt = 0; tt < 2; tt++) {
        int t = warp * 2 + tt;
        float s = 0.f;
        #pragma unroll
        for (int c = 0; c < 7; c++) {
            int w = lane + 32 * c;
            if (w < WW) s += sev[w * SEVST + t];
        }
        #pragma unroll
        for (int o = 16; o; o >>= 1) s += __shfl_xor_sync(0xffffffffu, s, o);
        if (lane == 0) ssum[t] = s;
    }
    __syncthreads();

    // ---- out: warps 0..15, warp = t-quad, lane = e-chunk (full 128 e) ----
    if (warp < 16) {
        const float norm = smisc[0];
        u64 o2[8] = {0, 0, 0, 0, 0, 0, 0, 0};   // 4 t x (2 u64 = 4 e)
        #pragma unroll 2
        for (int w = 0; w < WW; w++) {
            F4U a4; a4.v = *reinterpret_cast<const float4*>(sev + w * SEVST + warp * 4); // bcast
            F4U kv; kv.v = reinterpret_cast<const float4*>(sk + w * PADROW)[lane];
            #pragma unroll
            for (int tt = 0; tt < 4; tt++) {
                u64 av = pk2(a4.f[tt], a4.f[tt]);
                o2[2 * tt]     = fma2(av, kv.p[0], o2[2 * tt]);
                o2[2 * tt + 1] = fma2(av, kv.p[1], o2[2 * tt + 1]);
            }
        }
        #pragma unroll
        for (int tt = 0; tt < 4; tt++) {
            int t = warp * 4 + tt;
            float scale = 1.0f / (ssum[t] * norm);
            F4U r;
            unpk2(o2[2 * tt],     r.f[0], r.f[1]);
            unpk2(o2[2 * tt + 1], r.f[2], r.f[3]);
            r.f[0] *= scale; r.f[1] *= scale; r.f[2] *= scale; r.f[3] *= scale;
            reinterpret_cast<float4*>(out + (size_t)(b * TT + t) * EE)[lane] = r.v;
        }
    }
}

// =====================================================================
extern "C" void kernel_launch(void* const* d_in, const int* in_sizes, int n_in,
                              void* d_out, int out_size)
{
    const float* tvecs = (const float*)d_in[0];
    const float* cvecs = (const float*)d_in[1];
    const float* W_w   = (const float*)d_in[2];
    const float* W_b   = (const float*)d_in[3];
    const float* h_w   = (const float*)d_in[4];
    // d_in[5] = h_b: softmax-invariant, unused
    const int* titems  = (const int*)d_in[6];
    const int* citems  = (const int*)d_in[7];
    const uint32_t* mask = (const uint32_t*)d_in[8];
    float* out = (float*)d_out;

    cudaFuncSetAttribute(prep_kernel, cudaFuncAttributeMaxDynamicSharedMemorySize, SMEM_A_BYTES);
    cudaFuncSetAttribute(main_kernel, cudaFuncAttributeMaxDynamicSharedMemorySize, SMEM_B_BYTES);

    prep_kernel<<<BB, 256, SMEM_A_BYTES>>>(tvecs, W_w, h_w, titems);
    main_kernel<<<BB, THREADS, SMEM_B_BYTES>>>(cvecs, W_w, W_b, h_w, citems, mask, out);
}

// round 14
// speedup vs baseline: 1.1257x; 1.1257x over previous
#include <cuda_runtime.h>
#include <cstdint>

#define BB 128
#define TT 64
#define WW 200
#define EE 128
#define NN 128
#define PADROW 132   // row stride in floats
#define THREADS 1024

typedef unsigned long long u64;

// ---- f32x2 packed helpers ----
__device__ __forceinline__ u64 pk2(float lo, float hi) {
    u64 r; asm("mov.b64 %0,{%1,%2};" : "=l"(r) : "f"(lo), "f"(hi)); return r;
}
__device__ __forceinline__ u64 add2(u64 a, u64 b) {
    u64 r; asm("add.rn.f32x2 %0,%1,%2;" : "=l"(r) : "l"(a), "l"(b)); return r;
}
__device__ __forceinline__ u64 fma2(u64 a, u64 b, u64 c) {
    u64 r; asm("fma.rn.f32x2 %0,%1,%2,%3;" : "=l"(r) : "l"(a), "l"(b), "l"(c)); return r;
}
__device__ __forceinline__ void unpk2(u64 p, float& lo, float& hi) {
    asm("mov.b64 {%0,%1},%2;" : "=f"(lo), "=f"(hi) : "l"(p));
}
union F4U { float4 v; u64 p[2]; float f[4]; };

#define ABS2 0x7FFFFFFF7FFFFFFFULL

// ---- device scratch ----
__device__ float g_hpS[BB * TT * NN];   // hp[b,t,n] * |hw[n]|
__device__ float g_u[NN];               // u[e] = sum_n hw[n] * Wq[n,e]
__device__ float g_att[BB * WW * TT];   // exp'd attention, layout [b][w][t]

// =====================================================================
// Kernel A: hpS precompute (+ u vector from block 0)
// =====================================================================
#define SMEM_A_BYTES ((128 * PADROW + 64 * 128) * 4)

__global__ __launch_bounds__(256) void prep_kernel(
    const float* __restrict__ tvecs, const float* __restrict__ W_w,
    const float* __restrict__ h_w, const int* __restrict__ titems)
{
    extern __shared__ float sm[];
    float* sWp = sm;                 // [128][PADROW]
    float* sq  = sm + 128 * PADROW;  // [64][128]
    const int b = blockIdx.x, tid = threadIdx.x;

    for (int idx = tid; idx < 128 * 32; idx += 256) {
        int row = idx >> 5, c = idx & 31;
        float4 v = *reinterpret_cast<const float4*>(W_w + row * 256 + c * 4);
        float a = fabsf(h_w[row]);
        v.x *= a; v.y *= a; v.z *= a; v.w *= a;
        *reinterpret_cast<float4*>(sWp + row * PADROW + c * 4) = v;
    }
    for (int idx = tid; idx < 64 * 32; idx += 256) {
        int t = idx >> 5, c = idx & 31;
        int it = titems[b * TT + t];
        float4 v = *reinterpret_cast<const float4*>(tvecs + (size_t)it * EE + c * 4);
        *reinterpret_cast<float4*>(sq + t * 128 + c * 4) = v;
    }
    __syncthreads();

    for (int idx = tid; idx < TT * NN; idx += 256) {
        int n = idx & 127, t = idx >> 7;
        const F4U* qr = reinterpret_cast<const F4U*>(sq + t * 128);
        const F4U* wr = reinterpret_cast<const F4U*>(sWp + n * PADROW);
        u64 acc = 0;
        #pragma unroll
        for (int c = 0; c < 32; c++) {
            F4U q = qr[c], w = wr[c];
            acc = fma2(q.p[0], w.p[0], acc);
            acc = fma2(q.p[1], w.p[1], acc);
        }
        float lo, hi; unpk2(acc, lo, hi);
        g_hpS[(b * TT + t) * NN + n] = lo + hi;
    }

    if (b == 0) {
        for (int e = tid; e < EE; e += 256) {
            float acc = 0.f;
            #pragma unroll 8
            for (int n = 0; n < NN; n++)
                acc = fmaf(h_w[n], W_w[n * 256 + 128 + e], acc);
            g_u[e] = acc;
        }
    }
}

// =====================================================================
// Kernel B: per-batch attention. One CTA per b, 1024 threads.
// =====================================================================
#define OFF_SK 0                       // k       [200][132]
#define OFF_HQ (WW * PADROW)           // hqS     [200][132]; sev[w][68] in 4b
#define OFF_UN (2 * WW * PADROW)       // scratch: Wq tile [16][132] / sHp [16][132]
#define OFF_SU (OFF_UN + 3264)         // u       [128]
#define OFF_BQ (OFF_SU + 128)          // 0.5*Bq  [200] (+8 pad)
#define OFF_WB (OFF_BQ + 208)          // Wb*|hw| [128]
#define OFF_MK (OFF_WB + 128)          // mask flags (1B per w; 56 floats)
#define OFF_MS (OFF_MK + 56)           // misc [8]: [0]=norm
#define OFF_SUMS (OFF_MS + 8)          // per-t exp sums [64]
#define SMEM_B_FLOATS (OFF_SUMS + 64)
#define SMEM_B_BYTES (SMEM_B_FLOATS * 4)
#define SEVST 68                       // sev row stride (floats)

__global__ __launch_bounds__(THREADS, 1) void main_kernel(
    const float* __restrict__ cvecs, const float* __restrict__ W_w,
    const float* __restrict__ W_b,   const float* __restrict__ h_w,
    const int* __restrict__ citems,  const uint32_t* __restrict__ mask,
    float* __restrict__ out)
{
    extern __shared__ float sm[];
    float* sk    = sm + OFF_SK;
    float* shq   = sm + OFF_HQ;   // hq in phases 3-4a; sev in 4b
    float* sWq   = sm + OFF_UN;   // Wq tile in 3; sHp in 4a
    float* su    = sm + OFF_SU;
    float* sBq   = sm + OFF_BQ;
    float* swb   = sm + OFF_WB;
    unsigned char* smask = reinterpret_cast<unsigned char*>(sm + OFF_MK);
    float* smisc = sm + OFF_MS;
    float* ssum  = sm + OFF_SUMS;

    const int b = blockIdx.x, tid = threadIdx.x;
    const int warp = tid >> 5, lane = tid & 31;

    // ---- phase 1: loads ----
    if (tid < WW) smask[tid] = (mask[b * WW + tid] != 0u) ? 1 : 0;
    if (tid >= 256 && tid < 256 + 128) {
        int n = tid - 256;
        swb[n] = W_b[n] * fabsf(h_w[n]);
    }
    if (tid >= 384 && tid < 384 + 32) {
        int c = tid - 384;
        reinterpret_cast<float4*>(su)[c] = reinterpret_cast<const float4*>(g_u)[c];
    }
    for (int r = warp; r < WW; r += 32) {
        int idx = citems[b * WW + r];
        float4 v = reinterpret_cast<const float4*>(cvecs + (size_t)idx * EE)[lane];
        reinterpret_cast<float4*>(sk + r * PADROW)[lane] = v;
    }
    __syncthreads();

    // ---- phase 2: 0.5*Bq[w] = 0.5*k[w]·u ; mask count -> norm ----
    if (tid < WW) {
        const F4U* kr = reinterpret_cast<const F4U*>(sk + tid * PADROW);
        const F4U* ur = reinterpret_cast<const F4U*>(su);
        u64 acc = 0;
        #pragma unroll
        for (int c = 0; c < 32; c++) {
            F4U k = kr[c], u = ur[c];
            acc = fma2(k.p[0], u.p[0], acc);
            acc = fma2(k.p[1], u.p[1], acc);
        }
        float lo, hi; unpk2(acc, lo, hi);
        sBq[tid] = 0.5f * (lo + hi);
    }
    if (warp == 16) {
        int s = 0;
        #pragma unroll
        for (int c = 0; c < 7; c++) {
            int w = lane + 32 * c;
            if (w < WW) s += (int)smask[w];
        }
        #pragma unroll
        for (int o = 16; o; o >>= 1) s += __shfl_xor_sync(0xffffffffu, s, o);
        if (lane == 0) smisc[0] = sqrtf(1000.0f - (float)s);
    }

    // ---- phase 3: hqS = (k·Wq + Wb)*|hw|, 8 n-tiles of 16, 2w x 2n blocking ----
    for (int tile = 0; tile < 8; tile++) {
        __syncthreads();
        if (tid < 512) {
            int row = tid >> 5, c = tid & 31;  // 16 rows x 32 float4-chunks
            int n = tile * 16 + row;
            float4 v = *reinterpret_cast<const float4*>(W_w + n * 256 + 128 + c * 4);
            float a = fabsf(h_w[n]);
            v.x *= a; v.y *= a; v.z *= a; v.w *= a;
            *reinterpret_cast<float4*>(sWq + row * PADROW + c * 4) = v;
        }
        __syncthreads();
        if (tid < 800) {
            int wp = tid >> 3, nq = tid & 7;   // w in {wp, wp+100}, n-local in {nq, nq+8}
            const F4U* kA = reinterpret_cast<const F4U*>(sk + wp * PADROW);
            const F4U* kB = reinterpret_cast<const F4U*>(sk + (wp + 100) * PADROW);
            const F4U* wA = reinterpret_cast<const F4U*>(sWq + nq * PADROW);
            const F4U* wB = reinterpret_cast<const F4U*>(sWq + (nq + 8) * PADROW);
            u64 aA0 = 0, aA1 = 0, aB0 = 0, aB1 = 0;
            #pragma unroll
            for (int c = 0; c < 32; c++) {
                F4U ka = kA[c], kb = kB[c], xa = wA[c], xb = wB[c];
                aA0 = fma2(ka.p[0], xa.p[0], aA0); aA0 = fma2(ka.p[1], xa.p[1], aA0);
                aA1 = fma2(ka.p[0], xb.p[0], aA1); aA1 = fma2(ka.p[1], xb.p[1], aA1);
                aB0 = fma2(kb.p[0], xa.p[0], aB0); aB0 = fma2(kb.p[1], xa.p[1], aB0);
                aB1 = fma2(kb.p[0], xb.p[0], aB1); aB1 = fma2(kb.p[1], xb.p[1], aB1);
            }
            float lo, hi;
            int n0 = tile * 16 + nq, n1 = n0 + 8;
            unpk2(aA0, lo, hi); shq[wp * PADROW + n0]         = lo + hi + swb[n0];
            unpk2(aA1, lo, hi); shq[wp * PADROW + n1]         = lo + hi + swb[n1];
            unpk2(aB0, lo, hi); shq[(wp + 100) * PADROW + n0] = lo + hi + swb[n0];
            unpk2(aB1, lo, hi); shq[(wp + 100) * PADROW + n1] = lo + hi + swb[n1];
        }
    }

    // ---- phase 4a: ev = exp(logit). q-outer (R10 form), dual accumulators,
    //      ev batched 4 t -> one STG.128 into g_att[b][w][t] ----
    const int j = lane & 7, g = lane >> 3;
    u64 sgn2[8];
    #pragma unroll
    for (int c = 0; c < 4; c++) {
        F4U h; h.v = reinterpret_cast<const float4*>(h_w)[j + 8 * c];
        sgn2[2 * c]     = pk2(h.f[0] >= 0.f ? 0.5f : -0.5f, h.f[1] >= 0.f ? 0.5f : -0.5f);
        sgn2[2 * c + 1] = pk2(h.f[2] >= 0.f ? 0.5f : -0.5f, h.f[3] >= 0.f ? 0.5f : -0.5f);
    }
    float* gatt = g_att + (size_t)b * WW * TT;
    const float* hpbase = g_hpS + (size_t)b * TT * NN;
    float* sHp = sWq;   // [16][PADROW]

    for (int qtr = 0; qtr < 4; qtr++) {
        __syncthreads();   // sHp/sWq free
        if (warp < 16) {
            float4 v = reinterpret_cast<const float4*>(hpbase + (qtr * 16 + warp) * NN)[lane];
            reinterpret_cast<float4*>(sHp + warp * PADROW)[lane] = v;
        }
        __syncthreads();

        #pragma unroll 1
        for (int qi = 0; qi < 2; qi++) {
            int q;
            if (qi == 0) q = warp;
            else {
                int r = (warp + 8 * qtr) & 31;   // rotate extra-quad owners per quarter
                if (r >= 18) continue;           // warp-uniform; no barrier inside
                q = 32 + r;
            }
            const int w = 4 * q + g;
            u64 hq2[8];
            {
                const float4* hr = reinterpret_cast<const float4*>(shq + w * PADROW);
                #pragma unroll
                for (int c = 0; c < 4; c++) {
                    F4U x; x.v = hr[j + 8 * c];
                    hq2[2 * c] = x.p[0]; hq2[2 * c + 1] = x.p[1];
                }
            }
            const float bq = sBq[w];
            const int msk = smask[w];

            #pragma unroll 1
            for (int t4 = 0; t4 < 4; t4++) {
                F4U evv;
                #pragma unroll
                for (int tt = 0; tt < 4; tt++) {
                    int t2 = t4 * 4 + tt;
                    const float4* hpr = reinterpret_cast<const float4*>(sHp + t2 * PADROW);
                    u64 acc0 = 0, acc1 = 0;
                    #pragma unroll
                    for (int c = 0; c < 4; c++) {
                        F4U x; x.v = hpr[j + 8 * c];
                        u64 v0 = add2(x.p[0], hq2[2 * c]) & ABS2;
                        u64 v1 = add2(x.p[1], hq2[2 * c + 1]) & ABS2;
                        acc0 = fma2(v0, sgn2[2 * c], acc0);
                        acc1 = fma2(v1, sgn2[2 * c + 1], acc1);
                    }
                    u64 a = add2(acc0, acc1);
                    float lo, hi; unpk2(a, lo, hi);
                    float s = lo + hi;
                    s += __shfl_down_sync(0xffffffffu, s, 4, 8);
                    s += __shfl_down_sync(0xffffffffu, s, 2, 8);
                    s += __shfl_down_sync(0xffffffffu, s, 1, 8);
                    evv.f[tt] = msk ? 0.f : __expf(s + bq);   // valid at j==0
                }
                if (j == 0)
                    *reinterpret_cast<float4*>(gatt + w * TT + qtr * 16 + t4 * 4) = evv.v;
            }
        }
    }
    __syncthreads();   // g_att complete; shq (hq) now dead

    // ---- phase 4b: stage ev -> sev[w][68]; coalesced LDG.128 + STS.128 ----
    float* sev = shq;
    for (int idx = tid; idx < WW * 16; idx += THREADS) {   // (w, t-quad) pairs
        int w = idx >> 4, tq = idx & 15;
        float4 v = *reinterpret_cast<const float4*>(gatt + w * TT + 4 * tq);
        *reinterpret_cast<float4*>(sev + w * SEVST + 4 * tq) = v;
    }
    __syncthreads();

    // ---- sums: warp owns t = 2*warp, 2*warp+1 ----
    #pragma unroll
    for (int tt = 0; tt < 2; tt++) {
        int t = warp * 2 + tt;
        float s = 0.f;
        #pragma unroll
        for (int c = 0; c < 7; c++) {
            int w = lane + 32 * c;
            if (w < WW) s += sev[w * SEVST + t];
        }
        #pragma unroll
        for (int o = 16; o; o >>= 1) s += __shfl_xor_sync(0xffffffffu, s, o);
        if (lane == 0) ssum[t] = s;
    }
    __syncthreads();

    // ---- out: 32 warps, warp = (t-quad, e-half); lane = e-pair within half ----
    {
        const float norm = smisc[0];
        const int tq = warp >> 1, eh = warp & 1;
        u64 o2[4] = {0, 0, 0, 0};   // 4 t, one float2 per lane
        const float* skh = sk + eh * 64 + lane * 2;
        #pragma unroll 4
        for (int w = 0; w < WW; w++) {
            F4U a4; a4.v = *reinterpret_cast<const float4*>(sev + w * SEVST + tq * 4);  // bcast
            u64 kv = *reinterpret_cast<const u64*>(skh + w * PADROW);
            #pragma unroll
            for (int tt = 0; tt < 4; tt++) {
                u64 av = pk2(a4.f[tt], a4.f[tt]);
                o2[tt] = fma2(av, kv, o2[tt]);
            }
        }
        #pragma unroll
        for (int tt = 0; tt < 4; tt++) {
            int t = tq * 4 + tt;
            float scale = 1.0f / (ssum[t] * norm);
            float lo, hi; unpk2(o2[tt], lo, hi);
            float2 r; r.x = lo * scale; r.y = hi * scale;
            *reinterpret_cast<float2*>(out + (size_t)(b * TT + t) * EE + eh * 64 + lane * 2) = r;
        }
    }
}

// =====================================================================
extern "C" void kernel_launch(void* const* d_in, const int* in_sizes, int n_in,
                              void* d_out, int out_size)
{
    const float* tvecs = (const float*)d_in[0];
    const float* cvecs = (const float*)d_in[1];
    const float* W_w   = (const float*)d_in[2];
    const float* W_b   = (const float*)d_in[3];
    const float* h_w   = (const float*)d_in[4];
    // d_in[5] = h_b: softmax-invariant, unused
    const int* titems  = (const int*)d_in[6];
    const int* citems  = (const int*)d_in[7];
    const uint32_t* mask = (const uint32_t*)d_in[8];
    float* out = (float*)d_out;

    cudaFuncSetAttribute(prep_kernel, cudaFuncAttributeMaxDynamicSharedMemorySize, SMEM_A_BYTES);
    cudaFuncSetAttribute(main_kernel, cudaFuncAttributeMaxDynamicSharedMemorySize, SMEM_B_BYTES);

    prep_kernel<<<BB, 256, SMEM_A_BYTES>>>(tvecs, W_w, h_w, titems);
    main_kernel<<<BB, THREADS, SMEM_B_BYTES>>>(cvecs, W_w, W_b, h_w, citems, mask, out);
}